// round 1
// baseline (speedup 1.0000x reference)
#include <cuda_runtime.h>
#include <cuda_bf16.h>
#include <math.h>

// ---------------- problem constants ----------------
#define B_SZ   256
#define C1     256          // conv1 out channels
#define H1     20           // conv1 out spatial
#define C2     256          // conv2 out channels (G*PD)
#define H2     6
#define GS     36           // 6*6
#define G_NUM  32
#define PD     8
#define OC     10
#define OD     16
#define KGEMM  (256*81)     // 20736
#define NGEMM  (B_SZ*GS)    // 9216

// ---------------- scratch (device globals, no runtime alloc) ----------------
__device__ float g_x1[(size_t)B_SZ * C1 * H1 * H1];      // conv1 output (105 MB)
__device__ float g_y2[(size_t)B_SZ * C2 * GS];           // conv2 output (9.4 MB)
__device__ float g_u [(size_t)B_SZ * G_NUM * GS * PD];   // squashed primary caps
__device__ float g_vg[(size_t)B_SZ * G_NUM * OC * OD];   // per-group routed v

// ================= conv1: 1->256, 9x9, stride 1, + relu =================
// one block per image, 256 threads = out channels
__global__ void conv1_kernel(const float* __restrict__ inp,
                             const float* __restrict__ W1,
                             const float* __restrict__ b1) {
    extern __shared__ float sh[];
    float* s_in = sh;          // 784 (pad to 800)
    float* s_w  = sh + 800;    // 256*81 = 20736
    const int b = blockIdx.x;
    const int t = threadIdx.x;

    for (int i = t; i < 784; i += 256) s_in[i] = inp[b * 784 + i];
    for (int i = t; i < 20736; i += 256) s_w[i] = W1[i];
    __syncthreads();

    const int oc = t;
    const float bias = b1[oc];
    const float* w = s_w + oc * 81;
    float* outb = g_x1 + ((size_t)b * C1 + oc) * (H1 * H1);

    for (int oh = 0; oh < H1; ++oh) {
        float acc[20];
#pragma unroll
        for (int ow = 0; ow < 20; ++ow) acc[ow] = bias;
#pragma unroll
        for (int kh = 0; kh < 9; ++kh) {
            const float* row = s_in + (oh + kh) * 28;
            float r[28];
#pragma unroll
            for (int i = 0; i < 28; ++i) r[i] = row[i];
#pragma unroll
            for (int kw = 0; kw < 9; ++kw) {
                const float wv = w[kh * 9 + kw];
#pragma unroll
                for (int ow = 0; ow < 20; ++ow) acc[ow] = fmaf(wv, r[ow + kw], acc[ow]);
            }
        }
        float* op = outb + oh * 20;
#pragma unroll
        for (int ow = 0; ow < 20; ++ow) op[ow] = fmaxf(acc[ow], 0.f);
    }
}

// ================= conv2 as implicit GEMM =================
// C[m,n] = sum_k A[m,k]*B[k,n]; m=oc (256), n=b*36+s (9216), k=ic*81+kh*9+kw (20736)
// B[k,n] = x1[base_n(n) + off_k(k)]
#define BM 128
#define BN 128
#define BK 16

__global__ void conv2_gemm_kernel(const float* __restrict__ W2) {
    __shared__ float As[BK][BM];
    __shared__ float Bs[BK][BN];
    __shared__ int   s_base_n[BN];
    __shared__ int   s_off_k[BK];

    const int tid = threadIdx.x;          // 256 threads
    const int m0 = blockIdx.y * BM;
    const int n0 = blockIdx.x * BN;
    const int ty = tid >> 4;              // 0..15
    const int tx = tid & 15;              // 0..15

    if (tid < BN) {
        int n = n0 + tid;
        int b = n / 36, s = n - b * 36;
        int oh = s / 6, ow = s - oh * 6;
        s_base_n[tid] = b * (C1 * H1 * H1) + oh * 40 + ow * 2;
    }

    float acc[8][8];
#pragma unroll
    for (int i = 0; i < 8; ++i)
#pragma unroll
        for (int j = 0; j < 8; ++j) acc[i][j] = 0.f;

    for (int k0 = 0; k0 < KGEMM; k0 += BK) {
        __syncthreads();
        if (tid < BK) {
            int k = k0 + tid;
            int ic = k / 81; int r = k - ic * 81;
            int kh = r / 9;  int kw = r - kh * 9;
            s_off_k[tid] = ic * 400 + kh * 20 + kw;
        }
        __syncthreads();  // s_off_k ready (also covers s_base_n on first iter)

        // A tile: 128x16 = 512 float4, 2 per thread, store transposed [k][m]
#pragma unroll
        for (int r = 0; r < 2; ++r) {
            int f = tid + r * 256;
            int m = f >> 2;
            int kq = (f & 3) * 4;
            float4 v = *(const float4*)(W2 + (size_t)(m0 + m) * KGEMM + k0 + kq);
            As[kq + 0][m] = v.x; As[kq + 1][m] = v.y;
            As[kq + 2][m] = v.z; As[kq + 3][m] = v.w;
        }
        // B tile: 16x128 gather, 8 per thread
#pragma unroll
        for (int r = 0; r < 8; ++r) {
            int e = tid + r * 256;
            int k = e >> 7;
            int n = e & 127;
            Bs[k][n] = g_x1[s_base_n[n] + s_off_k[k]];
        }
        __syncthreads();

#pragma unroll
        for (int kk = 0; kk < BK; ++kk) {
            float a[8], bb[8];
#pragma unroll
            for (int i = 0; i < 8; ++i) a[i] = As[kk][ty * 8 + i];
#pragma unroll
            for (int j = 0; j < 8; ++j) bb[j] = Bs[kk][tx * 8 + j];
#pragma unroll
            for (int i = 0; i < 8; ++i)
#pragma unroll
                for (int j = 0; j < 8; ++j) acc[i][j] = fmaf(a[i], bb[j], acc[i][j]);
        }
    }

    // write back: g_y2[b][m][s]
#pragma unroll
    for (int j = 0; j < 8; ++j) {
        int n = n0 + tx * 8 + j;
        int b = n / 36, s = n - b * 36;
        float* dst = g_y2 + (size_t)b * (C2 * GS) + s;
#pragma unroll
        for (int i = 0; i < 8; ++i) {
            int m = m0 + ty * 8 + i;
            dst[m * GS] = acc[i][j];
        }
    }
}

// ================= primary caps: +bias, reshape, squash =================
__global__ void squash_primary_kernel(const float* __restrict__ b2) {
    int idx = blockIdx.x * blockDim.x + threadIdx.x;   // over B*G*GS
    if (idx >= B_SZ * G_NUM * GS) return;
    int s = idx % GS; int t = idx / GS;
    int g = t & 31;   int b = t >> 5;
    float v[PD]; float l2 = 0.f;
#pragma unroll
    for (int pd = 0; pd < PD; ++pd) {
        int oc = g * PD + pd;
        float y = g_y2[(size_t)b * (C2 * GS) + oc * GS + s] + b2[oc];
        v[pd] = y; l2 += y * y;
    }
    float l = sqrtf(l2);
    float scale = l2 / ((1.f + l2) * (l + 1e-8f));
#pragma unroll
    for (int pd = 0; pd < PD; ++pd) g_u[(size_t)idx * PD + pd] = v[pd] * scale;
}

// ================= capsule predictions + dynamic routing =================
// block = (g, 8 images); Wcaps[g] staged in smem
#define BT 8
__global__ void routing_kernel(const float* __restrict__ Wcaps,
                               const float* __restrict__ b_route) {
    extern __shared__ float sh[];
    float* s_w   = sh;                 // 46080
    float* s_up  = s_w  + 46080;       // 5760
    float* s_u   = s_up + 5760;        // 288
    float* s_b   = s_u  + 288;         // 360
    float* s_c   = s_b  + 360;         // 360
    float* s_v   = s_c  + 360;         // 160
    float* s_sv  = s_v  + 160;         // 160
    float* s_nrm = s_sv + 160;         // 16

    const int g   = blockIdx.x >> 5;   // /(B/BT)=32
    const int bt  = blockIdx.x & 31;
    const int tid = threadIdx.x;       // 256

    const float4* wsrc = (const float4*)(Wcaps + (size_t)g * 46080);
    float4* wdst = (float4*)s_w;
    for (int i = tid; i < 11520; i += 256) wdst[i] = wsrc[i];

    for (int img = 0; img < BT; ++img) {
        const int b = bt * BT + img;
        __syncthreads();   // previous image done with s_u/s_up; first iter: s_w loaded
        for (int i = tid; i < 288; i += 256)
            s_u[i] = g_u[(size_t)(b * G_NUM + g) * (GS * PD) + i];
        for (int i = tid; i < 360; i += 256)
            s_b[i] = b_route[g * 360 + i];
        __syncthreads();

        // up[s][o*16+d]
        for (int idx = tid; idx < 5760; idx += 256) {
            int s = idx / 160; int j = idx - s * 160;
            float a = 0.f;
#pragma unroll
            for (int i = 0; i < 8; ++i)
                a = fmaf(s_u[s * 8 + i], s_w[(s * 8 + i) * 160 + j], a);
            s_up[idx] = a;
        }
        __syncthreads();

        for (int it = 0; it < 3; ++it) {
            if (tid < GS) {             // softmax over OC per s-row
                float mx = -1e30f;
#pragma unroll
                for (int o = 0; o < OC; ++o) mx = fmaxf(mx, s_b[tid * OC + o]);
                float e[OC]; float sum = 0.f;
#pragma unroll
                for (int o = 0; o < OC; ++o) { e[o] = expf(s_b[tid * OC + o] - mx); sum += e[o]; }
                float inv = 1.f / sum;
#pragma unroll
                for (int o = 0; o < OC; ++o) s_c[tid * OC + o] = e[o] * inv;
            }
            __syncthreads();
            if (tid < OC * OD) {        // s[o][d]
                int o = tid >> 4;
                float a = 0.f;
                for (int s2 = 0; s2 < GS; ++s2)
                    a = fmaf(s_c[s2 * OC + o], s_up[s2 * 160 + tid], a);
                s_sv[tid] = a;
            }
            __syncthreads();
            if (tid < OC) {
                float l2 = 0.f;
#pragma unroll
                for (int d = 0; d < OD; ++d) { float x = s_sv[tid * OD + d]; l2 += x * x; }
                float l = sqrtf(l2);
                s_nrm[tid] = l2 / ((1.f + l2) * (l + 1e-8f));
            }
            __syncthreads();
            if (tid < OC * OD) s_v[tid] = s_sv[tid] * s_nrm[tid >> 4];
            __syncthreads();
            if (it < 2) {
                if (tid < GS * OC) {
                    int s2 = tid / OC; int o = tid - s2 * OC;
                    float a = 0.f;
#pragma unroll
                    for (int d = 0; d < OD; ++d)
                        a = fmaf(s_up[s2 * 160 + o * OD + d], s_v[o * OD + d], a);
                    s_b[tid] += a;
                }
                __syncthreads();
            }
        }
        if (tid < OC * OD)
            g_vg[(size_t)(b * G_NUM + g) * (OC * OD) + tid] = s_v[tid];
    }
}

// ================= finalize: sum over groups, probs =================
__global__ void finalize_kernel(float* __restrict__ out) {
    __shared__ float sv[OC * OD];
    const int b = blockIdx.x;
    const int tid = threadIdx.x;   // 160
    float a = 0.f;
    for (int g = 0; g < G_NUM; ++g)
        a += g_vg[(size_t)(b * G_NUM + g) * (OC * OD) + tid];
    out[b * (OC * OD) + tid] = a;
    sv[tid] = a;
    __syncthreads();
    if (tid < OC) {
        float l2 = 0.f;
#pragma unroll
        for (int d = 0; d < OD; ++d) { float x = sv[tid * OD + d]; l2 += x * x; }
        out[B_SZ * OC * OD + b * OC + tid] = sqrtf(l2);
    }
}

// ================= launch =================
extern "C" void kernel_launch(void* const* d_in, const int* in_sizes, int n_in,
                              void* d_out, int out_size) {
    const float* inp     = (const float*)d_in[0];
    const float* W1      = (const float*)d_in[1];
    const float* b1      = (const float*)d_in[2];
    const float* W2      = (const float*)d_in[3];
    const float* b2      = (const float*)d_in[4];
    const float* Wcaps   = (const float*)d_in[5];
    const float* b_route = (const float*)d_in[6];
    float* out = (float*)d_out;

    const int conv1_smem = (800 + 20736) * 4;                 // 86144 B
    const int route_smem = (46080 + 5760 + 288 + 360 + 360 + 160 + 160 + 16) * 4; // 212736 B
    cudaFuncSetAttribute(conv1_kernel,  cudaFuncAttributeMaxDynamicSharedMemorySize, conv1_smem);
    cudaFuncSetAttribute(routing_kernel, cudaFuncAttributeMaxDynamicSharedMemorySize, route_smem);

    conv1_kernel<<<B_SZ, 256, conv1_smem>>>(inp, W1, b1);

    dim3 g2(NGEMM / BN, C1 / BM);   // (72, 2)
    conv2_gemm_kernel<<<g2, 256>>>(W2);

    squash_primary_kernel<<<(B_SZ * G_NUM * GS + 255) / 256, 256>>>(b2);

    routing_kernel<<<G_NUM * (B_SZ / BT), 256, route_smem>>>(Wcaps, b_route);

    finalize_kernel<<<B_SZ, OC * OD>>>(out);
}

// round 3
// speedup vs baseline: 4.1301x; 4.1301x over previous
#include <cuda_runtime.h>
#include <cuda_bf16.h>
#include <math.h>
#include <stdint.h>

// ---------------- problem constants ----------------
#define B_SZ   256
#define C1     256
#define H1     20
#define C2     256
#define GS     36
#define G_NUM  32
#define PD     8
#define OC     10
#define OD     16
#define KGEMM  (256*81)     // 20736
#define NGEMM  (B_SZ*GS)    // 9216
#define NCHUNK (KGEMM/64)   // 324

// ---------------- scratch ----------------
__device__ __nv_bfloat16 g_x1h[(size_t)B_SZ * H1 * H1 * C1];   // conv1 out hi, NHWC
__device__ __nv_bfloat16 g_x1l[(size_t)B_SZ * H1 * H1 * C1];   // conv1 out lo
__device__ __nv_bfloat16 g_w2h[(size_t)C1 * KGEMM];            // W2 hi, [m][k'], k'=(kh*9+kw)*256+ic
__device__ __nv_bfloat16 g_w2l[(size_t)C1 * KGEMM];            // W2 lo
__device__ float g_y2[(size_t)B_SZ * C2 * GS];
__device__ float g_u [(size_t)B_SZ * G_NUM * GS * PD];
__device__ float g_vg[(size_t)B_SZ * G_NUM * OC * OD];

// ---------------- helpers ----------------
__device__ __forceinline__ uint32_t smem_u32(const void* p) {
    uint32_t a;
    asm("{ .reg .u64 t; cvta.to.shared.u64 t, %1; cvt.u32.u64 %0, t; }" : "=r"(a) : "l"(p));
    return a;
}
__device__ __forceinline__ void cpasync16(uint32_t dst, const void* src) {
    asm volatile("cp.async.cg.shared.global [%0], [%1], 16;" :: "r"(dst), "l"(src));
}
#define CP_COMMIT()  asm volatile("cp.async.commit_group;" ::: "memory")
#define CP_WAIT(N)   asm volatile("cp.async.wait_group " #N ";" ::: "memory")

__device__ __forceinline__ void ldsm4(uint32_t* r, uint32_t addr) {
    asm volatile("ldmatrix.sync.aligned.m8n8.x4.shared.b16 {%0,%1,%2,%3}, [%4];"
        : "=r"(r[0]), "=r"(r[1]), "=r"(r[2]), "=r"(r[3]) : "r"(addr));
}
__device__ __forceinline__ void mma16816(float* d, const uint32_t* a, const uint32_t* b) {
    asm volatile(
        "mma.sync.aligned.m16n8k16.row.col.f32.bf16.bf16.f32 "
        "{%0,%1,%2,%3}, {%4,%5,%6,%7}, {%8,%9}, {%0,%1,%2,%3};"
        : "+f"(d[0]), "+f"(d[1]), "+f"(d[2]), "+f"(d[3])
        : "r"(a[0]), "r"(a[1]), "r"(a[2]), "r"(a[3]), "r"(b[0]), "r"(b[1]));
}
__device__ __forceinline__ int swz(int byte) { return byte ^ ((byte >> 3) & 0x70); }

// ================= conv1: 1->256, 9x9, s1, relu; emit NHWC bf16 hi/lo =================
__global__ void conv1_kernel(const float* __restrict__ inp,
                             const float* __restrict__ W1,
                             const float* __restrict__ b1) {
    extern __shared__ float sh[];
    float* s_in = sh;          // 784
    float* s_w  = sh + 800;    // 20736
    const int b = blockIdx.x;
    const int t = threadIdx.x;

    for (int i = t; i < 784; i += 256) s_in[i] = inp[b * 784 + i];
    for (int i = t; i < 20736; i += 256) s_w[i] = W1[i];
    __syncthreads();

    const int oc = t;
    const float bias = b1[oc];
    const float* w = s_w + oc * 81;
    const size_t obase = (size_t)b * (H1 * H1 * C1) + oc;

    for (int oh = 0; oh < H1; ++oh) {
        float acc[20];
#pragma unroll
        for (int ow = 0; ow < 20; ++ow) acc[ow] = bias;
#pragma unroll
        for (int kh = 0; kh < 9; ++kh) {
            const float* row = s_in + (oh + kh) * 28;
            float r[28];
#pragma unroll
            for (int i = 0; i < 28; ++i) r[i] = row[i];
#pragma unroll
            for (int kw = 0; kw < 9; ++kw) {
                const float wv = w[kh * 9 + kw];
#pragma unroll
                for (int ow = 0; ow < 20; ++ow) acc[ow] = fmaf(wv, r[ow + kw], acc[ow]);
            }
        }
#pragma unroll
        for (int ow = 0; ow < 20; ++ow) {
            float v = fmaxf(acc[ow], 0.f);
            __nv_bfloat16 h = __float2bfloat16(v);
            __nv_bfloat16 l = __float2bfloat16(v - __bfloat162float(h));
            size_t o = obase + (size_t)(oh * 20 + ow) * 256;
            g_x1h[o] = h;
            g_x1l[o] = l;
        }
    }
}

// ================= W2 -> bf16 hi/lo, k' = (kh*9+kw)*256 + ic =================
__global__ void w2_convert_kernel(const float* __restrict__ W2) {
    int idx = blockIdx.x * 256 + threadIdx.x;
    if (idx >= C1 * KGEMM) return;
    int m = idx / KGEMM; int kp = idx - m * KGEMM;
    int khw = kp >> 8;   int ic = kp & 255;
    float w = W2[(size_t)m * KGEMM + ic * 81 + khw];
    __nv_bfloat16 h = __float2bfloat16(w);
    g_w2h[idx] = h;
    g_w2l[idx] = __float2bfloat16(w - __bfloat162float(h));
}

// ================= conv2: mma.sync bf16 split-3 implicit GEMM =================
// D[m,n] = sum_k' A[m,k'] B[n,k']; CTA 128x128, K chunks of 64, double-buffered cp.async
#define STAGE_BYTES 65536
#define AH_OFF 0
#define AL_OFF 16384
#define BH_OFF 32768
#define BL_OFF 49152

__global__ __launch_bounds__(256, 1) void conv2_mma_kernel() {
    extern __shared__ char smem[];
    const uint32_t sb = smem_u32(smem) + 1024;   // tiles base
    int* base_n = (int*)smem;
    const int tid = threadIdx.x;
    const int wid = tid >> 5, lane = tid & 31;
    const int m0 = blockIdx.y * 128;
    const int n0 = blockIdx.x * 128;
    const int wm = wid & 1;      // 2 m-slabs of 64
    const int wn = wid >> 1;     // 4 n-slabs of 32

    if (tid < 128) {
        int n = n0 + tid;
        int b = n / 36, s = n - b * 36;
        int oh = s / 6, ow = s - oh * 6;
        base_n[tid] = b * 102400 + (oh * 40 + ow * 2) * 256;
    }
    __syncthreads();

    // per-thread load indices: 4 segments each for A and B tiles
    const int e_m   = tid >> 3;        // row 0..31 (+32*p)
    const int e_seg = tid & 7;         // 16B segment within 128B row

    // ldmatrix source addresses (within a tile), depend on lane only
    const int a_row = (lane & 15);
    const int a_hi  = (lane >> 4) << 4;            // byte offset 0/16
    const int b_row = ((lane >> 4) << 3) + (lane & 7);
    const int b_hi  = ((lane >> 3) & 1) << 4;

    float acc[4][4][4];
#pragma unroll
    for (int i = 0; i < 4; ++i)
#pragma unroll
        for (int j = 0; j < 4; ++j)
#pragma unroll
            for (int r = 0; r < 4; ++r) acc[i][j][r] = 0.f;

    // ---- preload chunk 0 ----
    {
        const int c = 0;
        char* dummy = 0; (void)dummy;
        const uint32_t tb = sb;   // buf 0
        const int khw = c >> 2, icq = c & 3;
        const int kh = khw / 9, kw = khw - kh * 9;
        const int boff = (kh * 20 + kw) * 256 + icq * 64;
#pragma unroll
        for (int p = 0; p < 4; ++p) {
            int row = e_m + p * 32;
            int sw = swz(row * 128 + e_seg * 16);
            size_t asrc = (size_t)(m0 + row) * KGEMM + c * 64 + e_seg * 8;
            cpasync16(tb + AH_OFF + sw, g_w2h + asrc);
            cpasync16(tb + AL_OFF + sw, g_w2l + asrc);
            size_t bsrc = (size_t)base_n[row] + boff + e_seg * 8;
            cpasync16(tb + BH_OFF + sw, g_x1h + bsrc);
            cpasync16(tb + BL_OFF + sw, g_x1l + bsrc);
        }
        CP_COMMIT();
    }

    for (int c = 0; c < NCHUNK; ++c) {
        // ---- preload c+1 into other buffer ----
        if (c + 1 < NCHUNK) {
            const int cn = c + 1;
            const uint32_t tb = sb + (cn & 1) * STAGE_BYTES;
            const int khw = cn >> 2, icq = cn & 3;
            const int kh = khw / 9, kw = khw - kh * 9;
            const int boff = (kh * 20 + kw) * 256 + icq * 64;
#pragma unroll
            for (int p = 0; p < 4; ++p) {
                int row = e_m + p * 32;
                int sw = swz(row * 128 + e_seg * 16);
                size_t asrc = (size_t)(m0 + row) * KGEMM + cn * 64 + e_seg * 8;
                cpasync16(tb + AH_OFF + sw, g_w2h + asrc);
                cpasync16(tb + AL_OFF + sw, g_w2l + asrc);
                size_t bsrc = (size_t)base_n[row] + boff + e_seg * 8;
                cpasync16(tb + BH_OFF + sw, g_x1h + bsrc);
                cpasync16(tb + BL_OFF + sw, g_x1l + bsrc);
            }
            CP_COMMIT();
            CP_WAIT(1);
        } else {
            CP_WAIT(0);
        }
        __syncthreads();

        // ---- compute chunk c ----
        const uint32_t tb = sb + (c & 1) * STAGE_BYTES;
#pragma unroll
        for (int ks = 0; ks < 4; ++ks) {
            const int kb = ks * 32;
            uint32_t ah[4][4], al[4][4], bh[4][2], bl[4][2];
#pragma unroll
            for (int i = 0; i < 4; ++i) {
                int row = wm * 64 + i * 16 + a_row;
                uint32_t ad = tb + swz(row * 128 + kb + a_hi);
                ldsm4(ah[i], AH_OFF + ad);
                ldsm4(al[i], AL_OFF + ad);
            }
#pragma unroll
            for (int jp = 0; jp < 2; ++jp) {
                int row = wn * 32 + jp * 16 + b_row;
                uint32_t bd = tb + swz(row * 128 + kb + b_hi);
                uint32_t t0[4], t1[4];
                ldsm4(t0, BH_OFF + bd);
                ldsm4(t1, BL_OFF + bd);
                bh[jp*2][0] = t0[0]; bh[jp*2][1] = t0[1];
                bh[jp*2+1][0] = t0[2]; bh[jp*2+1][1] = t0[3];
                bl[jp*2][0] = t1[0]; bl[jp*2][1] = t1[1];
                bl[jp*2+1][0] = t1[2]; bl[jp*2+1][1] = t1[3];
            }
#pragma unroll
            for (int i = 0; i < 4; ++i)
#pragma unroll
                for (int j = 0; j < 4; ++j) {
                    mma16816(acc[i][j], ah[i], bh[j]);
                    mma16816(acc[i][j], ah[i], bl[j]);
                    mma16816(acc[i][j], al[i], bh[j]);
                }
        }
        __syncthreads();
    }

    // ---- epilogue: write g_y2[b][m][s] ----
    const int gq = lane >> 2, tig = lane & 3;
#pragma unroll
    for (int i = 0; i < 4; ++i) {
        int m = m0 + wm * 64 + i * 16 + gq;
#pragma unroll
        for (int j = 0; j < 4; ++j) {
            int n = n0 + wn * 32 + j * 8 + tig * 2;
            int b0 = n / 36, s0 = n - b0 * 36;
            int b1 = (n + 1) / 36, s1 = (n + 1) - b1 * 36;
            g_y2[(size_t)(b0 * 256 + m) * 36 + s0]     = acc[i][j][0];
            g_y2[(size_t)(b1 * 256 + m) * 36 + s1]     = acc[i][j][1];
            g_y2[(size_t)(b0 * 256 + m + 8) * 36 + s0] = acc[i][j][2];
            g_y2[(size_t)(b1 * 256 + m + 8) * 36 + s1] = acc[i][j][3];
        }
    }
}

// ================= primary caps squash =================
__global__ void squash_primary_kernel(const float* __restrict__ b2) {
    int idx = blockIdx.x * blockDim.x + threadIdx.x;
    if (idx >= B_SZ * G_NUM * GS) return;
    int s = idx % GS; int t = idx / GS;
    int g = t & 31;   int b = t >> 5;
    float v[PD]; float l2 = 0.f;
#pragma unroll
    for (int pd = 0; pd < PD; ++pd) {
        int oc = g * PD + pd;
        float y = g_y2[(size_t)b * (C2 * GS) + oc * GS + s] + b2[oc];
        v[pd] = y; l2 += y * y;
    }
    float l = sqrtf(l2);
    float scale = l2 / ((1.f + l2) * (l + 1e-8f));
#pragma unroll
    for (int pd = 0; pd < PD; ++pd) g_u[(size_t)idx * PD + pd] = v[pd] * scale;
}

// ================= capsule predictions + routing =================
#define BT 8
__global__ void routing_kernel(const float* __restrict__ Wcaps,
                               const float* __restrict__ b_route) {
    extern __shared__ float sh[];
    float* s_w   = sh;
    float* s_up  = s_w  + 46080;
    float* s_u   = s_up + 5760;
    float* s_b   = s_u  + 288;
    float* s_c   = s_b  + 360;
    float* s_v   = s_c  + 360;
    float* s_sv  = s_v  + 160;
    float* s_nrm = s_sv + 160;

    const int g   = blockIdx.x >> 5;
    const int bt  = blockIdx.x & 31;
    const int tid = threadIdx.x;

    const float4* wsrc = (const float4*)(Wcaps + (size_t)g * 46080);
    float4* wdst = (float4*)s_w;
    for (int i = tid; i < 11520; i += 256) wdst[i] = wsrc[i];

    for (int img = 0; img < BT; ++img) {
        const int b = bt * BT + img;
        __syncthreads();
        for (int i = tid; i < 288; i += 256)
            s_u[i] = g_u[(size_t)(b * G_NUM + g) * (GS * PD) + i];
        for (int i = tid; i < 360; i += 256)
            s_b[i] = b_route[g * 360 + i];
        __syncthreads();

        for (int idx = tid; idx < 5760; idx += 256) {
            int s = idx / 160; int j = idx - s * 160;
            float a = 0.f;
#pragma unroll
            for (int i = 0; i < 8; ++i)
                a = fmaf(s_u[s * 8 + i], s_w[(s * 8 + i) * 160 + j], a);
            s_up[idx] = a;
        }
        __syncthreads();

        for (int it = 0; it < 3; ++it) {
            if (tid < GS) {
                float mx = -1e30f;
#pragma unroll
                for (int o = 0; o < OC; ++o) mx = fmaxf(mx, s_b[tid * OC + o]);
                float e[OC]; float sum = 0.f;
#pragma unroll
                for (int o = 0; o < OC; ++o) { e[o] = expf(s_b[tid * OC + o] - mx); sum += e[o]; }
                float inv = 1.f / sum;
#pragma unroll
                for (int o = 0; o < OC; ++o) s_c[tid * OC + o] = e[o] * inv;
            }
            __syncthreads();
            if (tid < OC * OD) {
                int o = tid >> 4;
                float a = 0.f;
                for (int s2 = 0; s2 < GS; ++s2)
                    a = fmaf(s_c[s2 * OC + o], s_up[s2 * 160 + tid], a);
                s_sv[tid] = a;
            }
            __syncthreads();
            if (tid < OC) {
                float l2 = 0.f;
#pragma unroll
                for (int d = 0; d < OD; ++d) { float x = s_sv[tid * OD + d]; l2 += x * x; }
                float l = sqrtf(l2);
                s_nrm[tid] = l2 / ((1.f + l2) * (l + 1e-8f));
            }
            __syncthreads();
            if (tid < OC * OD) s_v[tid] = s_sv[tid] * s_nrm[tid >> 4];
            __syncthreads();
            if (it < 2) {
                if (tid < GS * OC) {
                    int s2 = tid / OC; int o = tid - s2 * OC;
                    float a = 0.f;
#pragma unroll
                    for (int d = 0; d < OD; ++d)
                        a = fmaf(s_up[s2 * 160 + o * OD + d], s_v[o * OD + d], a);
                    s_b[tid] += a;
                }
                __syncthreads();
            }
        }
        if (tid < OC * OD)
            g_vg[(size_t)(b * G_NUM + g) * (OC * OD) + tid] = s_v[tid];
    }
}

// ================= finalize =================
__global__ void finalize_kernel(float* __restrict__ out) {
    __shared__ float sv[OC * OD];
    const int b = blockIdx.x;
    const int tid = threadIdx.x;
    float a = 0.f;
    for (int g = 0; g < G_NUM; ++g)
        a += g_vg[(size_t)(b * G_NUM + g) * (OC * OD) + tid];
    out[b * (OC * OD) + tid] = a;
    sv[tid] = a;
    __syncthreads();
    if (tid < OC) {
        float l2 = 0.f;
#pragma unroll
        for (int d = 0; d < OD; ++d) { float x = sv[tid * OD + d]; l2 += x * x; }
        out[B_SZ * OC * OD + b * OC + tid] = sqrtf(l2);
    }
}

// ================= launch =================
extern "C" void kernel_launch(void* const* d_in, const int* in_sizes, int n_in,
                              void* d_out, int out_size) {
    const float* inp     = (const float*)d_in[0];
    const float* W1      = (const float*)d_in[1];
    const float* b1      = (const float*)d_in[2];
    const float* W2      = (const float*)d_in[3];
    const float* b2      = (const float*)d_in[4];
    const float* Wcaps   = (const float*)d_in[5];
    const float* b_route = (const float*)d_in[6];
    float* out = (float*)d_out;

    const int conv1_smem = (800 + 20736) * 4;
    const int conv2_smem = 1024 + 2 * STAGE_BYTES;   // 132096
    const int route_smem = (46080 + 5760 + 288 + 360 + 360 + 160 + 160 + 16) * 4;
    cudaFuncSetAttribute(conv1_kernel,     cudaFuncAttributeMaxDynamicSharedMemorySize, conv1_smem);
    cudaFuncSetAttribute(conv2_mma_kernel, cudaFuncAttributeMaxDynamicSharedMemorySize, conv2_smem);
    cudaFuncSetAttribute(routing_kernel,   cudaFuncAttributeMaxDynamicSharedMemorySize, route_smem);

    conv1_kernel<<<B_SZ, 256, conv1_smem>>>(inp, W1, b1);
    w2_convert_kernel<<<(C1 * KGEMM + 255) / 256, 256>>>(W2);

    dim3 g2(NGEMM / 128, C1 / 128);   // (72, 2)
    conv2_mma_kernel<<<g2, 256, conv2_smem>>>();

    squash_primary_kernel<<<(B_SZ * G_NUM * GS + 255) / 256, 256>>>(b2);
    routing_kernel<<<G_NUM * (B_SZ / BT), 256, route_smem>>>(Wcaps, b_route);
    finalize_kernel<<<B_SZ, OC * OD>>>(out);
}

// round 4
// speedup vs baseline: 4.3833x; 1.0613x over previous
#include <cuda_runtime.h>
#include <cuda_bf16.h>
#include <math.h>
#include <stdint.h>

// ---------------- problem constants ----------------
#define B_SZ   256
#define C1     256
#define H1     20
#define C2     256
#define GS     36
#define G_NUM  32
#define PD     8
#define OC     10
#define OD     16
#define KGEMM  (256*81)     // 20736
#define NGEMM  (B_SZ*GS)    // 9216
#define NCHUNK (KGEMM/64)   // 324
#define N1     (B_SZ*400)   // 102400 conv1 GEMM N

// ---------------- scratch ----------------
__device__ __nv_bfloat16 g_x1h[(size_t)N1 * C1];     // conv1 out hi, [(b*400+pix)][oc]
__device__ __nv_bfloat16 g_x1l[(size_t)N1 * C1];
__device__ __nv_bfloat16 g_w1h[(size_t)C1 * 96];     // W1 hi, padded K 81->96
__device__ __nv_bfloat16 g_w1l[(size_t)C1 * 96];
__device__ __nv_bfloat16 g_w2h[(size_t)C1 * KGEMM];  // W2 hi, [m][(khw)*256+ic]
__device__ __nv_bfloat16 g_w2l[(size_t)C1 * KGEMM];
__device__ float g_wt[(size_t)G_NUM * GS * 160 * 8]; // Wcaps transposed [g][s][j][i]
__device__ float g_y2[(size_t)NGEMM * C2];           // conv2 out [(b*36+s)][oc]
__device__ float g_vg[(size_t)B_SZ * G_NUM * OC * OD];

// ---------------- helpers ----------------
__device__ __forceinline__ uint32_t smem_u32(const void* p) {
    uint32_t a;
    asm("{ .reg .u64 t; cvta.to.shared.u64 t, %1; cvt.u32.u64 %0, t; }" : "=r"(a) : "l"(p));
    return a;
}
__device__ __forceinline__ void cpasync16(uint32_t dst, const void* src) {
    asm volatile("cp.async.cg.shared.global [%0], [%1], 16;" :: "r"(dst), "l"(src));
}
#define CP_COMMIT()  asm volatile("cp.async.commit_group;" ::: "memory")
#define CP_WAIT(N)   asm volatile("cp.async.wait_group " #N ";" ::: "memory")

__device__ __forceinline__ void ldsm4(uint32_t* r, uint32_t addr) {
    asm volatile("ldmatrix.sync.aligned.m8n8.x4.shared.b16 {%0,%1,%2,%3}, [%4];"
        : "=r"(r[0]), "=r"(r[1]), "=r"(r[2]), "=r"(r[3]) : "r"(addr));
}
__device__ __forceinline__ void mma16816(float* d, const uint32_t* a, const uint32_t* b) {
    asm volatile(
        "mma.sync.aligned.m16n8k16.row.col.f32.bf16.bf16.f32 "
        "{%0,%1,%2,%3}, {%4,%5,%6,%7}, {%8,%9}, {%0,%1,%2,%3};"
        : "+f"(d[0]), "+f"(d[1]), "+f"(d[2]), "+f"(d[3])
        : "r"(a[0]), "r"(a[1]), "r"(a[2]), "r"(a[3]), "r"(b[0]), "r"(b[1]));
}
__device__ __forceinline__ int swz(int byte) { return byte ^ ((byte >> 3) & 0x70); }
__device__ __forceinline__ uint32_t pack_hl(float v) {
    __nv_bfloat16 h = __float2bfloat16(v);
    __nv_bfloat16 l = __float2bfloat16(v - __bfloat162float(h));
    return (uint32_t)__bfloat16_as_ushort(h) | ((uint32_t)__bfloat16_as_ushort(l) << 16);
}

// ================= prep: W1 -> bf16 hi/lo padded =================
__global__ void prep_w1(const float* __restrict__ W1) {
    int idx = blockIdx.x * 256 + threadIdx.x;
    if (idx >= C1 * 96) return;
    int oc = idx / 96, k = idx - oc * 96;
    float w = (k < 81) ? W1[oc * 81 + k] : 0.f;
    __nv_bfloat16 h = __float2bfloat16(w);
    g_w1h[idx] = h;
    g_w1l[idx] = __float2bfloat16(w - __bfloat162float(h));
}

// ================= prep: Wcaps transpose [g][s][i][j] -> [g][s][j][i] =================
__global__ void prep_wt(const float* __restrict__ Wcaps) {
    __shared__ float t[8][161];
    const int gs = blockIdx.x;          // 0..1151
    const float* src = Wcaps + (size_t)gs * 1280;
    for (int e = threadIdx.x; e < 1280; e += 256) t[e / 160][e % 160] = src[e];
    __syncthreads();
    float* dst = g_wt + (size_t)gs * 1280;
    for (int e = threadIdx.x; e < 1280; e += 256) dst[e] = t[e & 7][e >> 3];
}

// ================= prep: W2 -> bf16 hi/lo with k' = khw*256+ic =================
__global__ void w2_convert_kernel(const float* __restrict__ W2) {
    extern __shared__ float sw[];     // 20736
    const int m = blockIdx.x, tid = threadIdx.x;
    for (int i = tid; i < 20736; i += 256) sw[i] = W2[(size_t)m * 20736 + i];
    __syncthreads();
    for (int t = tid; t < 2592; t += 256) {
        int base = t * 8;
        int khw = base >> 8, ic0 = base & 255;
        float v[8];
#pragma unroll
        for (int q = 0; q < 8; ++q) v[q] = sw[(ic0 + q) * 81 + khw];
        uint32_t hp[4], lp[4];
#pragma unroll
        for (int q = 0; q < 4; ++q) {
            __nv_bfloat16 h0 = __float2bfloat16(v[2*q]);
            __nv_bfloat16 h1 = __float2bfloat16(v[2*q+1]);
            __nv_bfloat16 l0 = __float2bfloat16(v[2*q]   - __bfloat162float(h0));
            __nv_bfloat16 l1 = __float2bfloat16(v[2*q+1] - __bfloat162float(h1));
            hp[q] = (uint32_t)__bfloat16_as_ushort(h0) | ((uint32_t)__bfloat16_as_ushort(h1) << 16);
            lp[q] = (uint32_t)__bfloat16_as_ushort(l0) | ((uint32_t)__bfloat16_as_ushort(l1) << 16);
        }
        *(uint4*)(g_w2h + (size_t)m * 20736 + base) = make_uint4(hp[0], hp[1], hp[2], hp[3]);
        *(uint4*)(g_w2l + (size_t)m * 20736 + base) = make_uint4(lp[0], lp[1], lp[2], lp[3]);
    }
}

// ================= conv1: split-3 bf16 HMMA implicit GEMM =================
// M=256 (oc), K=96 (81 pad), N=102400 (b*400 + oh*20 + ow); CTA 128x128
#define C1_IMG   0
#define C1_BASEN 6272
#define C1_OFFK  6784
#define C1_AH    7168
#define C1_AL    (C1_AH + 26624)
#define C1_BH    (C1_AL + 26624)
#define C1_BL    (C1_BH + 26624)
#define C1_SMEM  (C1_BL + 26624)     // 113664

__global__ __launch_bounds__(256, 2) void conv1_mma_kernel(const float* __restrict__ inp,
                                                           const float* __restrict__ b1) {
    extern __shared__ char smem[];
    float* s_img  = (float*)(smem + C1_IMG);
    int*   base_n = (int*)(smem + C1_BASEN);
    int*   off_k  = (int*)(smem + C1_OFFK);
    const uint32_t sb = smem_u32(smem);
    const int tid = threadIdx.x;
    const int wid = tid >> 5, lane = tid & 31;
    const int n0 = blockIdx.x * 128;
    const int m0 = blockIdx.y * 128;
    const int wm = wid & 1, wn = wid >> 1;
    const int bA = n0 / 400;

    // stage up to 2 raw images
    for (int i = tid; i < 1568; i += 256) {
        int bimg = bA + (i >= 784);
        s_img[i] = (bimg < B_SZ) ? inp[bimg * 784 + (i % 784)] : 0.f;
    }
    if (tid < 128) {
        int n = n0 + tid;
        int b = n / 400, r = n - b * 400;
        int oh = r / 20, ow = r - oh * 20;
        base_n[tid] = (b - bA) * 784 + oh * 28 + ow;
    }
    if (tid < 96) off_k[tid] = (tid < 81) ? (tid / 9) * 28 + (tid % 9) : -1;

    // A tiles: 128 rows x 96 bf16, pitch 208B
    {
        for (int p = 0; p < 6; ++p) {
            int f = tid + p * 256;            // 0..1535
            int row = f / 12, seg = f % 12;
            uint4 vh = *(const uint4*)(g_w1h + (size_t)(m0 + row) * 96 + seg * 8);
            uint4 vl = *(const uint4*)(g_w1l + (size_t)(m0 + row) * 96 + seg * 8);
            *(uint4*)(smem + C1_AH + row * 208 + seg * 16) = vh;
            *(uint4*)(smem + C1_AL + row * 208 + seg * 16) = vl;
        }
    }
    __syncthreads();

    // B build from staged image
    {
        const int row = tid >> 1;
        const int kb = (tid & 1) * 48;
        const int base = base_n[row];
        __nv_bfloat16* bh = (__nv_bfloat16*)(smem + C1_BH + row * 208);
        __nv_bfloat16* bl = (__nv_bfloat16*)(smem + C1_BL + row * 208);
#pragma unroll 8
        for (int kk = 0; kk < 48; ++kk) {
            int k = kb + kk;
            int off = off_k[k];
            float v = (off >= 0) ? s_img[base + off] : 0.f;
            __nv_bfloat16 h = __float2bfloat16(v);
            bh[k] = h;
            bl[k] = __float2bfloat16(v - __bfloat162float(h));
        }
    }
    __syncthreads();

    const int a_row = lane & 15, a_hi = (lane >> 4) << 4;
    const int b_row = ((lane >> 4) << 3) + (lane & 7), b_hi = ((lane >> 3) & 1) << 4;

    float acc[4][4][4];
#pragma unroll
    for (int i = 0; i < 4; ++i)
#pragma unroll
        for (int j = 0; j < 4; ++j)
#pragma unroll
            for (int r = 0; r < 4; ++r) acc[i][j][r] = 0.f;

#pragma unroll
    for (int ks = 0; ks < 6; ++ks) {
        const int kbyte = ks * 32;
        uint32_t ah[4][4], al[4][4], bhf[4][2], blf[4][2];
#pragma unroll
        for (int i = 0; i < 4; ++i) {
            int row = wm * 64 + i * 16 + a_row;
            uint32_t ad = sb + row * 208 + kbyte + a_hi;
            ldsm4(ah[i], C1_AH + ad);
            ldsm4(al[i], C1_AL + ad);
        }
#pragma unroll
        for (int jp = 0; jp < 2; ++jp) {
            int row = wn * 32 + jp * 16 + b_row;
            uint32_t bd = sb + row * 208 + kbyte + b_hi;
            uint32_t t0[4], t1[4];
            ldsm4(t0, C1_BH + bd);
            ldsm4(t1, C1_BL + bd);
            bhf[jp*2][0] = t0[0]; bhf[jp*2][1] = t0[1];
            bhf[jp*2+1][0] = t0[2]; bhf[jp*2+1][1] = t0[3];
            blf[jp*2][0] = t1[0]; blf[jp*2][1] = t1[1];
            blf[jp*2+1][0] = t1[2]; blf[jp*2+1][1] = t1[3];
        }
#pragma unroll
        for (int i = 0; i < 4; ++i)
#pragma unroll
            for (int j = 0; j < 4; ++j) {
                mma16816(acc[i][j], ah[i], bhf[j]);
                mma16816(acc[i][j], ah[i], blf[j]);
                mma16816(acc[i][j], al[i], bhf[j]);
            }
    }
    __syncthreads();

    // epilogue: bias+relu, pack h/l into u32, smem roundtrip, coalesced store
    uint32_t* s_out = (uint32_t*)(smem + C1_AH);   // 128n x 128m
    const int gq = lane >> 2, tig = lane & 3;
#pragma unroll
    for (int i = 0; i < 4; ++i) {
        int mloc = wm * 64 + i * 16 + gq;
        float b1a = __ldg(b1 + m0 + mloc), b1b = __ldg(b1 + m0 + mloc + 8);
#pragma unroll
        for (int j = 0; j < 4; ++j) {
            int nloc = wn * 32 + j * 8 + tig * 2;
            s_out[nloc * 128 + mloc]           = pack_hl(fmaxf(acc[i][j][0] + b1a, 0.f));
            s_out[(nloc + 1) * 128 + mloc]     = pack_hl(fmaxf(acc[i][j][1] + b1a, 0.f));
            s_out[nloc * 128 + mloc + 8]       = pack_hl(fmaxf(acc[i][j][2] + b1b, 0.f));
            s_out[(nloc + 1) * 128 + mloc + 8] = pack_hl(fmaxf(acc[i][j][3] + b1b, 0.f));
        }
    }
    __syncthreads();
#pragma unroll
    for (int t = 0; t < 8; ++t) {
        int f = tid + t * 256;               // 0..2047
        int nloc = f >> 4, seg = f & 15;
        uint4 p0 = *(uint4*)(s_out + nloc * 128 + seg * 8);
        uint4 p1 = *(uint4*)(s_out + nloc * 128 + seg * 8 + 4);
        uint4 hq, lq;
        hq.x = (p0.x & 0xFFFFu) | (p0.y << 16);
        hq.y = (p0.z & 0xFFFFu) | (p0.w << 16);
        hq.z = (p1.x & 0xFFFFu) | (p1.y << 16);
        hq.w = (p1.z & 0xFFFFu) | (p1.w << 16);
        lq.x = (p0.x >> 16) | (p0.y & 0xFFFF0000u);
        lq.y = (p0.z >> 16) | (p0.w & 0xFFFF0000u);
        lq.z = (p1.x >> 16) | (p1.y & 0xFFFF0000u);
        lq.w = (p1.z >> 16) | (p1.w & 0xFFFF0000u);
        size_t dst = (size_t)(n0 + nloc) * 256 + m0 + seg * 8;
        *(uint4*)(g_x1h + dst) = hq;
        *(uint4*)(g_x1l + dst) = lq;
    }
}

// ================= conv2: mma.sync bf16 split-3 implicit GEMM =================
#define STAGE_BYTES 65536
#define AH_OFF 0
#define AL_OFF 16384
#define BH_OFF 32768
#define BL_OFF 49152

__global__ __launch_bounds__(256, 1) void conv2_mma_kernel() {
    extern __shared__ char smem[];
    const uint32_t sb = smem_u32(smem) + 1024;
    int* base_n = (int*)smem;
    const int tid = threadIdx.x;
    const int wid = tid >> 5, lane = tid & 31;
    const int m0 = blockIdx.y * 128;
    const int n0 = blockIdx.x * 128;
    const int wm = wid & 1, wn = wid >> 1;

    if (tid < 128) {
        int n = n0 + tid;
        int b = n / 36, s = n - b * 36;
        int oh = s / 6, ow = s - oh * 6;
        base_n[tid] = b * 102400 + (oh * 40 + ow * 2) * 256;
    }
    __syncthreads();

    const int e_m = tid >> 3, e_seg = tid & 7;
    const int a_row = lane & 15, a_hi = (lane >> 4) << 4;
    const int b_row = ((lane >> 4) << 3) + (lane & 7), b_hi = ((lane >> 3) & 1) << 4;

    float acc[4][4][4];
#pragma unroll
    for (int i = 0; i < 4; ++i)
#pragma unroll
        for (int j = 0; j < 4; ++j)
#pragma unroll
            for (int r = 0; r < 4; ++r) acc[i][j][r] = 0.f;

    {
        const uint32_t tb = sb;
#pragma unroll
        for (int p = 0; p < 4; ++p) {
            int row = e_m + p * 32;
            int sw = swz(row * 128 + e_seg * 16);
            size_t asrc = (size_t)(m0 + row) * KGEMM + e_seg * 8;
            cpasync16(tb + AH_OFF + sw, g_w2h + asrc);
            cpasync16(tb + AL_OFF + sw, g_w2l + asrc);
            size_t bsrc = (size_t)base_n[row] + e_seg * 8;
            cpasync16(tb + BH_OFF + sw, g_x1h + bsrc);
            cpasync16(tb + BL_OFF + sw, g_x1l + bsrc);
        }
        CP_COMMIT();
    }

    for (int c = 0; c < NCHUNK; ++c) {
        if (c + 1 < NCHUNK) {
            const int cn = c + 1;
            const uint32_t tb = sb + (cn & 1) * STAGE_BYTES;
            const int khw = cn >> 2, icq = cn & 3;
            const int kh = khw / 9, kw = khw - kh * 9;
            const int boff = (kh * 20 + kw) * 256 + icq * 64;
#pragma unroll
            for (int p = 0; p < 4; ++p) {
                int row = e_m + p * 32;
                int sw = swz(row * 128 + e_seg * 16);
                size_t asrc = (size_t)(m0 + row) * KGEMM + cn * 64 + e_seg * 8;
                cpasync16(tb + AH_OFF + sw, g_w2h + asrc);
                cpasync16(tb + AL_OFF + sw, g_w2l + asrc);
                size_t bsrc = (size_t)base_n[row] + boff + e_seg * 8;
                cpasync16(tb + BH_OFF + sw, g_x1h + bsrc);
                cpasync16(tb + BL_OFF + sw, g_x1l + bsrc);
            }
            CP_COMMIT();
            CP_WAIT(1);
        } else {
            CP_WAIT(0);
        }
        __syncthreads();

        const uint32_t tb = sb + (c & 1) * STAGE_BYTES;
#pragma unroll
        for (int ks = 0; ks < 4; ++ks) {
            const int kb = ks * 32;
            uint32_t ah[4][4], al[4][4], bh[4][2], bl[4][2];
#pragma unroll
            for (int i = 0; i < 4; ++i) {
                int row = wm * 64 + i * 16 + a_row;
                uint32_t ad = tb + swz(row * 128 + kb + a_hi);
                ldsm4(ah[i], AH_OFF + ad);
                ldsm4(al[i], AL_OFF + ad);
            }
#pragma unroll
            for (int jp = 0; jp < 2; ++jp) {
                int row = wn * 32 + jp * 16 + b_row;
                uint32_t bd = tb + swz(row * 128 + kb + b_hi);
                uint32_t t0[4], t1[4];
                ldsm4(t0, BH_OFF + bd);
                ldsm4(t1, BL_OFF + bd);
                bh[jp*2][0] = t0[0]; bh[jp*2][1] = t0[1];
                bh[jp*2+1][0] = t0[2]; bh[jp*2+1][1] = t0[3];
                bl[jp*2][0] = t1[0]; bl[jp*2][1] = t1[1];
                bl[jp*2+1][0] = t1[2]; bl[jp*2+1][1] = t1[3];
            }
#pragma unroll
            for (int i = 0; i < 4; ++i)
#pragma unroll
                for (int j = 0; j < 4; ++j) {
                    mma16816(acc[i][j], ah[i], bh[j]);
                    mma16816(acc[i][j], ah[i], bl[j]);
                    mma16816(acc[i][j], al[i], bh[j]);
                }
        }
        __syncthreads();
    }

    // epilogue: g_y2[(b*36+s)][oc] = [n][m]
    const int gq = lane >> 2, tig = lane & 3;
#pragma unroll
    for (int i = 0; i < 4; ++i) {
        int m = m0 + wm * 64 + i * 16 + gq;
#pragma unroll
        for (int j = 0; j < 4; ++j) {
            int n = n0 + wn * 32 + j * 8 + tig * 2;
            g_y2[(size_t)n * 256 + m]           = acc[i][j][0];
            g_y2[(size_t)(n + 1) * 256 + m]     = acc[i][j][1];
            g_y2[(size_t)n * 256 + m + 8]       = acc[i][j][2];
            g_y2[(size_t)(n + 1) * 256 + m + 8] = acc[i][j][3];
        }
    }
}

// ================= routing: warp-per-image (fused squash) =================
// smem float offsets
#define R_UP  0
#define R_U   46080
#define R_B   48384
#define R_C   51264
#define R_V   54144
#define R_NRM 55424
#define R_TOT 55552

__global__ __launch_bounds__(256, 1) void routing_kernel(const float* __restrict__ b_route,
                                                         const float* __restrict__ b2) {
    extern __shared__ float sh[];
    const int tid = threadIdx.x;
    const int wid = tid >> 5, lane = tid & 31;
    const int g  = blockIdx.x >> 5;
    const int bt = blockIdx.x & 31;
    const int b  = bt * 8 + wid;

    float* up  = sh + R_UP  + wid * 5760;
    float* uu  = sh + R_U   + wid * 288;
    float* bb  = sh + R_B   + wid * 360;
    float* cc  = sh + R_C   + wid * 360;
    float* vv  = sh + R_V   + wid * 160;
    float* nrm = sh + R_NRM + wid * 16;

    // b2 slice for this group
    float b2v[8];
#pragma unroll
    for (int i = 0; i < 8; ++i) b2v[i] = __ldg(&b2[g * 8 + i]);

    // ---- u = squash(y2 + b2) ----
#pragma unroll
    for (int r = 0; r < 2; ++r) {
        int s = lane + 32 * r;
        if (s < 36) {
            const float* y = g_y2 + (size_t)(b * 36 + s) * 256 + g * 8;
            float4 y0 = *(const float4*)y;
            float4 y1 = *(const float4*)(y + 4);
            float v0 = y0.x + b2v[0], v1 = y0.y + b2v[1], v2 = y0.z + b2v[2], v3 = y0.w + b2v[3];
            float v4 = y1.x + b2v[4], v5 = y1.y + b2v[5], v6 = y1.z + b2v[6], v7 = y1.w + b2v[7];
            float l2 = v0*v0+v1*v1+v2*v2+v3*v3+v4*v4+v5*v5+v6*v6+v7*v7;
            float sc = l2 / ((1.f + l2) * (sqrtf(l2) + 1e-8f));
            float4 o0 = make_float4(v0*sc, v1*sc, v2*sc, v3*sc);
            float4 o1 = make_float4(v4*sc, v5*sc, v6*sc, v7*sc);
            *(float4*)(uu + s * 8)     = o0;
            *(float4*)(uu + s * 8 + 4) = o1;
        }
    }
    // b_route init
    {
        const float4* src = (const float4*)(b_route + g * 360);
#pragma unroll
        for (int r = 0; r < 3; ++r) {
            int f = lane + 32 * r;
            if (f < 90) ((float4*)bb)[f] = src[f];
        }
    }
    __syncwarp();

    // ---- up[s][j] = sum_i u[s][i] * Wt[g][s][j][i] ----
    for (int s = 0; s < 36; ++s) {
        float4 ua = *(const float4*)(uu + s * 8);
        float4 ub = *(const float4*)(uu + s * 8 + 4);
        const float* wrow = g_wt + ((size_t)(g * 36 + s) * 160) * 8;
#pragma unroll
        for (int q = 0; q < 5; ++q) {
            int j = lane + 32 * q;
            const float* wp = wrow + j * 8;
            float4 w0 = *(const float4*)wp;
            float4 w1 = *(const float4*)(wp + 4);
            float a = ua.x*w0.x + ua.y*w0.y + ua.z*w0.z + ua.w*w0.w
                    + ub.x*w1.x + ub.y*w1.y + ub.z*w1.z + ub.w*w1.w;
            up[s * 160 + j] = a;
        }
    }
    __syncwarp();

    // ---- 3 routing iterations ----
    float sv[5];
    for (int it = 0; it < 3; ++it) {
#pragma unroll
        for (int r = 0; r < 2; ++r) {
            int s = lane + 32 * r;
            if (s < 36) {
                float mx = -1e30f;
#pragma unroll
                for (int o = 0; o < OC; ++o) mx = fmaxf(mx, bb[s * 10 + o]);
                float e[OC]; float sum = 0.f;
#pragma unroll
                for (int o = 0; o < OC; ++o) { e[o] = expf(bb[s * 10 + o] - mx); sum += e[o]; }
                float inv = 1.f / sum;
#pragma unroll
                for (int o = 0; o < OC; ++o) cc[s * 10 + o] = e[o] * inv;
            }
        }
        __syncwarp();
#pragma unroll
        for (int q = 0; q < 5; ++q) {
            int od = lane + 32 * q;
            int o = od >> 4;
            float a = 0.f;
            for (int s = 0; s < 36; ++s)
                a = fmaf(cc[s * 10 + o], up[s * 160 + od], a);
            sv[q] = a;
            vv[od] = a;
        }
        __syncwarp();
        if (lane < OC) {
            float l2 = 0.f;
#pragma unroll
            for (int d = 0; d < OD; ++d) { float x = vv[lane * 16 + d]; l2 += x * x; }
            nrm[lane] = l2 / ((1.f + l2) * (sqrtf(l2) + 1e-8f));
        }
        __syncwarp();
#pragma unroll
        for (int q = 0; q < 5; ++q) {
            int od = lane + 32 * q;
            vv[od] = sv[q] * nrm[od >> 4];
        }
        __syncwarp();
        if (it < 2) {
#pragma unroll
            for (int r = 0; r < 12; ++r) {
                int e = lane + 32 * r;
                if (e < 360) {
                    int s = e / 10, o = e - s * 10;
                    float a = 0.f;
#pragma unroll
                    for (int d = 0; d < OD; ++d)
                        a = fmaf(up[s * 160 + o * 16 + d], vv[o * 16 + d], a);
                    bb[e] += a;
                }
            }
            __syncwarp();
        }
    }
    // write v
    float* dst = g_vg + (size_t)(b * G_NUM + g) * 160;
#pragma unroll
    for (int q = 0; q < 5; ++q) dst[lane + 32 * q] = vv[lane + 32 * q];
}

// ================= finalize =================
__global__ void finalize_kernel(float* __restrict__ out) {
    __shared__ float sv[OC * OD];
    const int b = blockIdx.x;
    const int tid = threadIdx.x;
    float a = 0.f;
    for (int g = 0; g < G_NUM; ++g)
        a += g_vg[(size_t)(b * G_NUM + g) * 160 + tid];
    out[b * 160 + tid] = a;
    sv[tid] = a;
    __syncthreads();
    if (tid < OC) {
        float l2 = 0.f;
#pragma unroll
        for (int d = 0; d < OD; ++d) { float x = sv[tid * 16 + d]; l2 += x * x; }
        out[B_SZ * 160 + b * OC + tid] = sqrtf(l2);
    }
}

// ================= launch =================
extern "C" void kernel_launch(void* const* d_in, const int* in_sizes, int n_in,
                              void* d_out, int out_size) {
    const float* inp     = (const float*)d_in[0];
    const float* W1      = (const float*)d_in[1];
    const float* b1      = (const float*)d_in[2];
    const float* W2      = (const float*)d_in[3];
    const float* b2      = (const float*)d_in[4];
    const float* Wcaps   = (const float*)d_in[5];
    const float* b_route = (const float*)d_in[6];
    float* out = (float*)d_out;

    const int w2_smem    = 20736 * 4;
    const int conv2_smem = 1024 + 2 * STAGE_BYTES;   // 132096
    const int route_smem = R_TOT * 4;                 // 222208
    cudaFuncSetAttribute(w2_convert_kernel, cudaFuncAttributeMaxDynamicSharedMemorySize, w2_smem);
    cudaFuncSetAttribute(conv1_mma_kernel,  cudaFuncAttributeMaxDynamicSharedMemorySize, C1_SMEM);
    cudaFuncSetAttribute(conv2_mma_kernel,  cudaFuncAttributeMaxDynamicSharedMemorySize, conv2_smem);
    cudaFuncSetAttribute(routing_kernel,    cudaFuncAttributeMaxDynamicSharedMemorySize, route_smem);

    prep_w1<<<(C1 * 96 + 255) / 256, 256>>>(W1);
    prep_wt<<<G_NUM * GS, 256>>>(Wcaps);
    w2_convert_kernel<<<C1, 256, w2_smem>>>(W2);

    dim3 g1(N1 / 128, 2);            // (800, 2)
    conv1_mma_kernel<<<g1, 256, C1_SMEM>>>(inp, b1);

    dim3 g2(NGEMM / 128, 2);         // (72, 2)
    conv2_mma_kernel<<<g2, 256, conv2_smem>>>();

    routing_kernel<<<G_NUM * 32, 256, route_smem>>>(b_route, b2);
    finalize_kernel<<<B_SZ, 160>>>(out);
}

// round 5
// speedup vs baseline: 4.6940x; 1.0709x over previous
#include <cuda_runtime.h>
#include <cuda_bf16.h>
#include <math.h>
#include <stdint.h>

// ---------------- problem constants ----------------
#define B_SZ   256
#define C1     256
#define H1     20
#define C2     256
#define GS     36
#define G_NUM  32
#define PD     8
#define OC     10
#define OD     16
#define KGEMM  (256*81)     // 20736
#define NGEMM  (B_SZ*GS)    // 9216
#define NCHUNK (KGEMM/64)   // 324
#define N1     (B_SZ*400)   // 102400

// ---------------- scratch ----------------
__device__ __nv_bfloat16 g_x1h[(size_t)N1 * C1];
__device__ __nv_bfloat16 g_x1l[(size_t)N1 * C1];
__device__ __nv_bfloat16 g_w1h[(size_t)C1 * 96];
__device__ __nv_bfloat16 g_w1l[(size_t)C1 * 96];
__device__ __nv_bfloat16 g_w2h[(size_t)C1 * KGEMM];
__device__ __nv_bfloat16 g_w2l[(size_t)C1 * KGEMM];
__device__ float g_y2[(size_t)NGEMM * C2];                     // [(b*36+s)][oc]
__device__ float g_up[(size_t)G_NUM * B_SZ * GS * 160];        // [g][b][s][od] 188MB
__device__ float g_vg[(size_t)B_SZ * G_NUM * OC * OD];

// ---------------- helpers ----------------
__device__ __forceinline__ uint32_t smem_u32(const void* p) {
    uint32_t a;
    asm("{ .reg .u64 t; cvta.to.shared.u64 t, %1; cvt.u32.u64 %0, t; }" : "=r"(a) : "l"(p));
    return a;
}
__device__ __forceinline__ void cpasync16(uint32_t dst, const void* src) {
    asm volatile("cp.async.cg.shared.global [%0], [%1], 16;" :: "r"(dst), "l"(src));
}
#define CP_COMMIT()  asm volatile("cp.async.commit_group;" ::: "memory")
#define CP_WAIT(N)   asm volatile("cp.async.wait_group " #N ";" ::: "memory")

__device__ __forceinline__ void ldsm4(uint32_t* r, uint32_t addr) {
    asm volatile("ldmatrix.sync.aligned.m8n8.x4.shared.b16 {%0,%1,%2,%3}, [%4];"
        : "=r"(r[0]), "=r"(r[1]), "=r"(r[2]), "=r"(r[3]) : "r"(addr));
}
__device__ __forceinline__ void mma16816(float* d, const uint32_t* a, const uint32_t* b) {
    asm volatile(
        "mma.sync.aligned.m16n8k16.row.col.f32.bf16.bf16.f32 "
        "{%0,%1,%2,%3}, {%4,%5,%6,%7}, {%8,%9}, {%0,%1,%2,%3};"
        : "+f"(d[0]), "+f"(d[1]), "+f"(d[2]), "+f"(d[3])
        : "r"(a[0]), "r"(a[1]), "r"(a[2]), "r"(a[3]), "r"(b[0]), "r"(b[1]));
}
__device__ __forceinline__ int swz(int byte) { return byte ^ ((byte >> 3) & 0x70); }
__device__ __forceinline__ uint32_t pack_hl(float v) {
    __nv_bfloat16 h = __float2bfloat16(v);
    __nv_bfloat16 l = __float2bfloat16(v - __bfloat162float(h));
    return (uint32_t)__bfloat16_as_ushort(h) | ((uint32_t)__bfloat16_as_ushort(l) << 16);
}

// ================= prep: W1 -> bf16 hi/lo padded =================
__global__ void prep_w1(const float* __restrict__ W1) {
    int idx = blockIdx.x * 256 + threadIdx.x;
    if (idx >= C1 * 96) return;
    int oc = idx / 96, k = idx - oc * 96;
    float w = (k < 81) ? W1[oc * 81 + k] : 0.f;
    __nv_bfloat16 h = __float2bfloat16(w);
    g_w1h[idx] = h;
    g_w1l[idx] = __float2bfloat16(w - __bfloat162float(h));
}

// ================= prep: W2 -> bf16 hi/lo with k' = khw*256+ic =================
__global__ void w2_convert_kernel(const float* __restrict__ W2) {
    extern __shared__ float sw[];     // 20736
    const int m = blockIdx.x, tid = threadIdx.x;
    for (int i = tid; i < 20736; i += 256) sw[i] = W2[(size_t)m * 20736 + i];
    __syncthreads();
    for (int t = tid; t < 2592; t += 256) {
        int base = t * 8;
        int khw = base >> 8, ic0 = base & 255;
        float v[8];
#pragma unroll
        for (int q = 0; q < 8; ++q) v[q] = sw[(ic0 + q) * 81 + khw];
        uint32_t hp[4], lp[4];
#pragma unroll
        for (int q = 0; q < 4; ++q) {
            __nv_bfloat16 h0 = __float2bfloat16(v[2*q]);
            __nv_bfloat16 h1 = __float2bfloat16(v[2*q+1]);
            __nv_bfloat16 l0 = __float2bfloat16(v[2*q]   - __bfloat162float(h0));
            __nv_bfloat16 l1 = __float2bfloat16(v[2*q+1] - __bfloat162float(h1));
            hp[q] = (uint32_t)__bfloat16_as_ushort(h0) | ((uint32_t)__bfloat16_as_ushort(h1) << 16);
            lp[q] = (uint32_t)__bfloat16_as_ushort(l0) | ((uint32_t)__bfloat16_as_ushort(l1) << 16);
        }
        *(uint4*)(g_w2h + (size_t)m * 20736 + base) = make_uint4(hp[0], hp[1], hp[2], hp[3]);
        *(uint4*)(g_w2l + (size_t)m * 20736 + base) = make_uint4(lp[0], lp[1], lp[2], lp[3]);
    }
}

// ================= conv1: split-3 bf16 HMMA implicit GEMM =================
#define C1_IMG   0
#define C1_BASEN 6272
#define C1_OFFK  6784
#define C1_AH    7168
#define C1_AL    (C1_AH + 26624)
#define C1_BH    (C1_AL + 26624)
#define C1_BL    (C1_BH + 26624)
#define C1_SMEM  (C1_BL + 26624)     // 113664

__global__ __launch_bounds__(256, 2) void conv1_mma_kernel(const float* __restrict__ inp,
                                                           const float* __restrict__ b1) {
    extern __shared__ char smem[];
    float* s_img  = (float*)(smem + C1_IMG);
    int*   base_n = (int*)(smem + C1_BASEN);
    int*   off_k  = (int*)(smem + C1_OFFK);
    const uint32_t sb = smem_u32(smem);
    const int tid = threadIdx.x;
    const int wid = tid >> 5, lane = tid & 31;
    const int n0 = blockIdx.x * 128;
    const int m0 = blockIdx.y * 128;
    const int wm = wid & 1, wn = wid >> 1;
    const int bA = n0 / 400;

    for (int i = tid; i < 1568; i += 256) {
        int bimg = bA + (i >= 784);
        s_img[i] = (bimg < B_SZ) ? inp[bimg * 784 + (i % 784)] : 0.f;
    }
    if (tid < 128) {
        int n = n0 + tid;
        int b = n / 400, r = n - b * 400;
        int oh = r / 20, ow = r - oh * 20;
        base_n[tid] = (b - bA) * 784 + oh * 28 + ow;
    }
    if (tid < 96) off_k[tid] = (tid < 81) ? (tid / 9) * 28 + (tid % 9) : -1;

    // A tiles: 128 rows x 96 bf16, pitch 208B
    for (int p = 0; p < 6; ++p) {
        int f = tid + p * 256;
        int row = f / 12, seg = f % 12;
        uint4 vh = *(const uint4*)(g_w1h + (size_t)(m0 + row) * 96 + seg * 8);
        uint4 vl = *(const uint4*)(g_w1l + (size_t)(m0 + row) * 96 + seg * 8);
        *(uint4*)(smem + C1_AH + row * 208 + seg * 16) = vh;
        *(uint4*)(smem + C1_AL + row * 208 + seg * 16) = vl;
    }
    __syncthreads();

    // B build, pairwise vectorized
    {
        const int row = tid >> 1;
        const int half = tid & 1;
        const int base = base_n[row];
        uint32_t* bh = (uint32_t*)(smem + C1_BH + row * 208) + half * 24;
        uint32_t* bl = (uint32_t*)(smem + C1_BL + row * 208) + half * 24;
#pragma unroll 6
        for (int kk = 0; kk < 24; ++kk) {
            int k = half * 48 + kk * 2;
            int o0 = off_k[k], o1 = off_k[k + 1];
            float v0 = (o0 >= 0) ? s_img[base + o0] : 0.f;
            float v1 = (o1 >= 0) ? s_img[base + o1] : 0.f;
            __nv_bfloat162 h2 = __floats2bfloat162_rn(v0, v1);
            float r0 = v0 - __bfloat162float(h2.x);
            float r1 = v1 - __bfloat162float(h2.y);
            __nv_bfloat162 l2v = __floats2bfloat162_rn(r0, r1);
            bh[kk] = *(uint32_t*)&h2;
            bl[kk] = *(uint32_t*)&l2v;
        }
    }
    __syncthreads();

    const int a_row = lane & 15, a_hi = (lane >> 4) << 4;
    const int b_row = ((lane >> 4) << 3) + (lane & 7), b_hi = ((lane >> 3) & 1) << 4;

    float acc[4][4][4];
#pragma unroll
    for (int i = 0; i < 4; ++i)
#pragma unroll
        for (int j = 0; j < 4; ++j)
#pragma unroll
            for (int r = 0; r < 4; ++r) acc[i][j][r] = 0.f;

#pragma unroll
    for (int ks = 0; ks < 6; ++ks) {
        const int kbyte = ks * 32;
        uint32_t ah[4][4], al[4][4], bhf[4][2], blf[4][2];
#pragma unroll
        for (int i = 0; i < 4; ++i) {
            int row = wm * 64 + i * 16 + a_row;
            uint32_t ad = sb + row * 208 + kbyte + a_hi;
            ldsm4(ah[i], C1_AH + ad);
            ldsm4(al[i], C1_AL + ad);
        }
#pragma unroll
        for (int jp = 0; jp < 2; ++jp) {
            int row = wn * 32 + jp * 16 + b_row;
            uint32_t bd = sb + row * 208 + kbyte + b_hi;
            uint32_t t0[4], t1[4];
            ldsm4(t0, C1_BH + bd);
            ldsm4(t1, C1_BL + bd);
            bhf[jp*2][0] = t0[0]; bhf[jp*2][1] = t0[1];
            bhf[jp*2+1][0] = t0[2]; bhf[jp*2+1][1] = t0[3];
            blf[jp*2][0] = t1[0]; blf[jp*2][1] = t1[1];
            blf[jp*2+1][0] = t1[2]; blf[jp*2+1][1] = t1[3];
        }
#pragma unroll
        for (int i = 0; i < 4; ++i)
#pragma unroll
            for (int j = 0; j < 4; ++j) {
                mma16816(acc[i][j], ah[i], bhf[j]);
                mma16816(acc[i][j], ah[i], blf[j]);
                mma16816(acc[i][j], al[i], bhf[j]);
            }
    }
    __syncthreads();

    uint32_t* s_out = (uint32_t*)(smem + C1_AH);
    const int gq = lane >> 2, tig = lane & 3;
#pragma unroll
    for (int i = 0; i < 4; ++i) {
        int mloc = wm * 64 + i * 16 + gq;
        float b1a = __ldg(b1 + m0 + mloc), b1b = __ldg(b1 + m0 + mloc + 8);
#pragma unroll
        for (int j = 0; j < 4; ++j) {
            int nloc = wn * 32 + j * 8 + tig * 2;
            s_out[nloc * 128 + mloc]           = pack_hl(fmaxf(acc[i][j][0] + b1a, 0.f));
            s_out[(nloc + 1) * 128 + mloc]     = pack_hl(fmaxf(acc[i][j][1] + b1a, 0.f));
            s_out[nloc * 128 + mloc + 8]       = pack_hl(fmaxf(acc[i][j][2] + b1b, 0.f));
            s_out[(nloc + 1) * 128 + mloc + 8] = pack_hl(fmaxf(acc[i][j][3] + b1b, 0.f));
        }
    }
    __syncthreads();
#pragma unroll
    for (int t = 0; t < 8; ++t) {
        int f = tid + t * 256;
        int nloc = f >> 4, seg = f & 15;
        uint4 p0 = *(uint4*)(s_out + nloc * 128 + seg * 8);
        uint4 p1 = *(uint4*)(s_out + nloc * 128 + seg * 8 + 4);
        uint4 hq, lq;
        hq.x = (p0.x & 0xFFFFu) | (p0.y << 16);
        hq.y = (p0.z & 0xFFFFu) | (p0.w << 16);
        hq.z = (p1.x & 0xFFFFu) | (p1.y << 16);
        hq.w = (p1.z & 0xFFFFu) | (p1.w << 16);
        lq.x = (p0.x >> 16) | (p0.y & 0xFFFF0000u);
        lq.y = (p0.z >> 16) | (p0.w & 0xFFFF0000u);
        lq.z = (p1.x >> 16) | (p1.y & 0xFFFF0000u);
        lq.w = (p1.z >> 16) | (p1.w & 0xFFFF0000u);
        size_t dst = (size_t)(n0 + nloc) * 256 + m0 + seg * 8;
        *(uint4*)(g_x1h + dst) = hq;
        *(uint4*)(g_x1l + dst) = lq;
    }
}

// ================= conv2: 3-stage mma.sync bf16 split-3 implicit GEMM =================
#define STAGE_BYTES 65536
#define AH_OFF 0
#define AL_OFF 16384
#define BH_OFF 32768
#define BL_OFF 49152

__global__ __launch_bounds__(256, 1) void conv2_mma_kernel() {
    extern __shared__ char smem[];
    const uint32_t sb = smem_u32(smem) + 1024;
    int* base_n = (int*)smem;
    const int tid = threadIdx.x;
    const int wid = tid >> 5, lane = tid & 31;
    const int m0 = blockIdx.y * 128;
    const int n0 = blockIdx.x * 128;
    const int wm = wid & 1, wn = wid >> 1;

    if (tid < 128) {
        int n = n0 + tid;
        int b = n / 36, s = n - b * 36;
        int oh = s / 6, ow = s - oh * 6;
        base_n[tid] = b * 102400 + (oh * 40 + ow * 2) * 256;
    }
    __syncthreads();

    const int e_m = tid >> 3, e_seg = tid & 7;
    const int a_row = lane & 15, a_hi = (lane >> 4) << 4;
    const int b_row = ((lane >> 4) << 3) + (lane & 7), b_hi = ((lane >> 3) & 1) << 4;

    auto preload = [&](int cc) {
        const uint32_t tb = sb + (cc % 3) * STAGE_BYTES;
        const int khw = cc >> 2, icq = cc & 3;
        const int kh = khw / 9, kw = khw - kh * 9;
        const int boff = (kh * 20 + kw) * 256 + icq * 64;
#pragma unroll
        for (int p = 0; p < 4; ++p) {
            int row = e_m + p * 32;
            int sw = swz(row * 128 + e_seg * 16);
            size_t asrc = (size_t)(m0 + row) * KGEMM + cc * 64 + e_seg * 8;
            cpasync16(tb + AH_OFF + sw, g_w2h + asrc);
            cpasync16(tb + AL_OFF + sw, g_w2l + asrc);
            size_t bsrc = (size_t)base_n[row] + boff + e_seg * 8;
            cpasync16(tb + BH_OFF + sw, g_x1h + bsrc);
            cpasync16(tb + BL_OFF + sw, g_x1l + bsrc);
        }
        CP_COMMIT();
    };

    float acc[4][4][4];
#pragma unroll
    for (int i = 0; i < 4; ++i)
#pragma unroll
        for (int j = 0; j < 4; ++j)
#pragma unroll
            for (int r = 0; r < 4; ++r) acc[i][j][r] = 0.f;

    preload(0);
    preload(1);

    for (int c = 0; c < NCHUNK; ++c) {
        if (c + 2 < NCHUNK) { CP_WAIT(1); } else { CP_WAIT(0); }
        __syncthreads();
        if (c + 2 < NCHUNK) preload(c + 2);

        const uint32_t tb = sb + (c % 3) * STAGE_BYTES;
#pragma unroll
        for (int ks = 0; ks < 4; ++ks) {
            const int kb = ks * 32;
            uint32_t ah[4][4], al[4][4], bh[4][2], bl[4][2];
#pragma unroll
            for (int i = 0; i < 4; ++i) {
                int row = wm * 64 + i * 16 + a_row;
                uint32_t ad = tb + swz(row * 128 + kb + a_hi);
                ldsm4(ah[i], AH_OFF + ad);
                ldsm4(al[i], AL_OFF + ad);
            }
#pragma unroll
            for (int jp = 0; jp < 2; ++jp) {
                int row = wn * 32 + jp * 16 + b_row;
                uint32_t bd = tb + swz(row * 128 + kb + b_hi);
                uint32_t t0[4], t1[4];
                ldsm4(t0, BH_OFF + bd);
                ldsm4(t1, BL_OFF + bd);
                bh[jp*2][0] = t0[0]; bh[jp*2][1] = t0[1];
                bh[jp*2+1][0] = t0[2]; bh[jp*2+1][1] = t0[3];
                bl[jp*2][0] = t1[0]; bl[jp*2][1] = t1[1];
                bl[jp*2+1][0] = t1[2]; bl[jp*2+1][1] = t1[3];
            }
#pragma unroll
            for (int i = 0; i < 4; ++i)
#pragma unroll
                for (int j = 0; j < 4; ++j) {
                    mma16816(acc[i][j], ah[i], bh[j]);
                    mma16816(acc[i][j], ah[i], bl[j]);
                    mma16816(acc[i][j], al[i], bh[j]);
                }
        }
    }

    const int gq = lane >> 2, tig = lane & 3;
#pragma unroll
    for (int i = 0; i < 4; ++i) {
        int m = m0 + wm * 64 + i * 16 + gq;
#pragma unroll
        for (int j = 0; j < 4; ++j) {
            int n = n0 + wn * 32 + j * 8 + tig * 2;
            g_y2[(size_t)n * 256 + m]           = acc[i][j][0];
            g_y2[(size_t)(n + 1) * 256 + m]     = acc[i][j][1];
            g_y2[(size_t)n * 256 + m + 8]       = acc[i][j][2];
            g_y2[(size_t)(n + 1) * 256 + m + 8] = acc[i][j][3];
        }
    }
}

// ================= caps_up: up[g][b][s][od] = squash(y2+b2) . Wcaps =================
__global__ __launch_bounds__(256, 1) void caps_up_kernel(const float* __restrict__ Wcaps,
                                                         const float* __restrict__ b2) {
    __shared__ float sW[1280];
    __shared__ float st[256 * 36];   // [b][od'] pad 36
    const int gs = blockIdx.x;               // 0..1151
    const int g = gs / 36, s = gs - g * 36;
    const int tid = threadIdx.x;             // = image b

    for (int i = tid; i < 1280; i += 256) sW[i] = Wcaps[(size_t)gs * 1280 + i];
    float b2v[8];
#pragma unroll
    for (int i = 0; i < 8; ++i) b2v[i] = __ldg(&b2[g * 8 + i]);
    __syncthreads();

    // squash
    float u[8];
    {
        const float* y = g_y2 + (size_t)(tid * 36 + s) * 256 + g * 8;
        float4 y0 = *(const float4*)y;
        float4 y1 = *(const float4*)(y + 4);
        u[0] = y0.x + b2v[0]; u[1] = y0.y + b2v[1]; u[2] = y0.z + b2v[2]; u[3] = y0.w + b2v[3];
        u[4] = y1.x + b2v[4]; u[5] = y1.y + b2v[5]; u[6] = y1.z + b2v[6]; u[7] = y1.w + b2v[7];
        float l2 = 0.f;
#pragma unroll
        for (int i = 0; i < 8; ++i) l2 += u[i] * u[i];
        float sc = l2 / ((1.f + l2) * (sqrtf(l2) + 1e-8f));
#pragma unroll
        for (int i = 0; i < 8; ++i) u[i] *= sc;
    }

    for (int ch = 0; ch < 5; ++ch) {
        const int od0 = ch * 32;
#pragma unroll
        for (int c4 = 0; c4 < 8; ++c4) {
            float4 a = make_float4(0.f, 0.f, 0.f, 0.f);
#pragma unroll
            for (int i = 0; i < 8; ++i) {
                float4 w = *(const float4*)(sW + i * 160 + od0 + c4 * 4);
                a.x = fmaf(u[i], w.x, a.x);
                a.y = fmaf(u[i], w.y, a.y);
                a.z = fmaf(u[i], w.z, a.z);
                a.w = fmaf(u[i], w.w, a.w);
            }
            *(float4*)(st + tid * 36 + c4 * 4) = a;
        }
        __syncthreads();
#pragma unroll
        for (int k = 0; k < 8; ++k) {
            int F = k * 256 + tid;
            int bp = F >> 3, c4 = F & 7;
            float4 v = *(const float4*)(st + bp * 36 + c4 * 4);
            *(float4*)(g_up + (size_t)(g * 256 + bp) * 5760 + s * 160 + od0 + c4 * 4) = v;
        }
        __syncthreads();
    }
}

// ================= routing: warp-per-image, up staged from global =================
#define RW_FLOATS 6656   // per-warp: up 5760 + bb 360 + cc 360 + vv 160 + nrm 16

__global__ __launch_bounds__(256, 1) void routing_kernel(const float* __restrict__ b_route) {
    extern __shared__ float sh[];
    const int tid = threadIdx.x;
    const int wid = tid >> 5, lane = tid & 31;
    const int g  = blockIdx.x >> 5;
    const int bt = blockIdx.x & 31;
    const int b  = bt * 8 + wid;

    float* up  = sh + wid * RW_FLOATS;
    float* bb  = up + 5760;
    float* cc  = bb + 360;
    float* vv  = cc + 360;
    float* nrm = vv + 160;

    // stage up (23KB) coalesced
    {
        const float4* src = (const float4*)(g_up + (size_t)(g * 256 + b) * 5760);
        float4* dst = (float4*)up;
#pragma unroll
        for (int q = 0; q < 45; ++q) dst[lane + 32 * q] = src[lane + 32 * q];
    }
    // b_route init
    {
        const float4* src = (const float4*)(b_route + g * 360);
#pragma unroll
        for (int r = 0; r < 3; ++r) {
            int f = lane + 32 * r;
            if (f < 90) ((float4*)bb)[f] = src[f];
        }
    }
    __syncwarp();

    float sv[5];
    for (int it = 0; it < 3; ++it) {
#pragma unroll
        for (int r = 0; r < 2; ++r) {
            int s = lane + 32 * r;
            if (s < 36) {
                float mx = -1e30f;
#pragma unroll
                for (int o = 0; o < OC; ++o) mx = fmaxf(mx, bb[s * 10 + o]);
                float e[OC]; float sum = 0.f;
#pragma unroll
                for (int o = 0; o < OC; ++o) { e[o] = expf(bb[s * 10 + o] - mx); sum += e[o]; }
                float inv = 1.f / sum;
#pragma unroll
                for (int o = 0; o < OC; ++o) cc[s * 10 + o] = e[o] * inv;
            }
        }
        __syncwarp();
#pragma unroll
        for (int q = 0; q < 5; ++q) {
            int od = lane + 32 * q;
            int o = od >> 4;
            float a = 0.f;
            for (int s = 0; s < 36; ++s)
                a = fmaf(cc[s * 10 + o], up[s * 160 + od], a);
            sv[q] = a;
            vv[od] = a;
        }
        __syncwarp();
        if (lane < OC) {
            float l2 = 0.f;
#pragma unroll
            for (int d = 0; d < OD; ++d) { float x = vv[lane * 16 + d]; l2 += x * x; }
            nrm[lane] = l2 / ((1.f + l2) * (sqrtf(l2) + 1e-8f));
        }
        __syncwarp();
#pragma unroll
        for (int q = 0; q < 5; ++q) {
            int od = lane + 32 * q;
            vv[od] = sv[q] * nrm[od >> 4];
        }
        __syncwarp();
        if (it < 2) {
#pragma unroll
            for (int r = 0; r < 12; ++r) {
                int e = lane + 32 * r;
                if (e < 360) {
                    int s = e / 10, o = e - s * 10;
                    float a = 0.f;
#pragma unroll
                    for (int d = 0; d < OD; ++d)
                        a = fmaf(up[s * 160 + o * 16 + d], vv[o * 16 + d], a);
                    bb[e] += a;
                }
            }
            __syncwarp();
        }
    }
    float* dst = g_vg + (size_t)(b * G_NUM + g) * 160;
#pragma unroll
    for (int q = 0; q < 5; ++q) dst[lane + 32 * q] = vv[lane + 32 * q];
}

// ================= finalize =================
__global__ void finalize_kernel(float* __restrict__ out) {
    __shared__ float sv[OC * OD];
    const int b = blockIdx.x;
    const int tid = threadIdx.x;
    float a = 0.f;
    for (int g = 0; g < G_NUM; ++g)
        a += g_vg[(size_t)(b * G_NUM + g) * 160 + tid];
    out[b * 160 + tid] = a;
    sv[tid] = a;
    __syncthreads();
    if (tid < OC) {
        float l2 = 0.f;
#pragma unroll
        for (int d = 0; d < OD; ++d) { float x = sv[tid * 16 + d]; l2 += x * x; }
        out[B_SZ * 160 + b * OC + tid] = sqrtf(l2);
    }
}

// ================= launch =================
extern "C" void kernel_launch(void* const* d_in, const int* in_sizes, int n_in,
                              void* d_out, int out_size) {
    const float* inp     = (const float*)d_in[0];
    const float* W1      = (const float*)d_in[1];
    const float* b1      = (const float*)d_in[2];
    const float* W2      = (const float*)d_in[3];
    const float* b2      = (const float*)d_in[4];
    const float* Wcaps   = (const float*)d_in[5];
    const float* b_route = (const float*)d_in[6];
    float* out = (float*)d_out;

    const int w2_smem    = 20736 * 4;
    const int conv2_smem = 1024 + 3 * STAGE_BYTES;   // 197632
    const int route_smem = 8 * RW_FLOATS * 4;        // 212992
    cudaFuncSetAttribute(w2_convert_kernel, cudaFuncAttributeMaxDynamicSharedMemorySize, w2_smem);
    cudaFuncSetAttribute(conv1_mma_kernel,  cudaFuncAttributeMaxDynamicSharedMemorySize, C1_SMEM);
    cudaFuncSetAttribute(conv2_mma_kernel,  cudaFuncAttributeMaxDynamicSharedMemorySize, conv2_smem);
    cudaFuncSetAttribute(routing_kernel,    cudaFuncAttributeMaxDynamicSharedMemorySize, route_smem);

    prep_w1<<<(C1 * 96 + 255) / 256, 256>>>(W1);
    w2_convert_kernel<<<C1, 256, w2_smem>>>(W2);

    dim3 g1(N1 / 128, 2);            // (800, 2)
    conv1_mma_kernel<<<g1, 256, C1_SMEM>>>(inp, b1);

    dim3 g2(NGEMM / 128, 2);         // (72, 2)
    conv2_mma_kernel<<<g2, 256, conv2_smem>>>();

    caps_up_kernel<<<G_NUM * GS, 256>>>(Wcaps, b2);
    routing_kernel<<<G_NUM * 32, 256, route_smem>>>(b_route);
    finalize_kernel<<<B_SZ, 160>>>(out);
}